// round 15
// baseline (speedup 1.0000x reference)
#include <cuda_runtime.h>
#include <math.h>
#include <stdint.h>

#define C_    384
#define HH    56
#define WW    56
#define HWSZ  3136
#define NB    16
#define EPSV  1e-5f

// Scratch for x_pw: 16*384*3136 floats = 77 MB
__device__ float g_xpw[(size_t)NB * C_ * HWSZ];

__device__ __forceinline__ uint32_t cvt_tf32(float f) {
    uint32_t r;
    asm("cvt.rna.tf32.f32 %0, %1;" : "=r"(r) : "f"(f));
    return r;
}

#define MMA_TF32(c, a, b) \
    asm volatile("mma.sync.aligned.m16n8k8.row.col.f32.tf32.tf32.f32 " \
        "{%0,%1,%2,%3}, {%4,%5,%6,%7}, {%8,%9}, {%0,%1,%2,%3};" \
        : "+f"((c)[0]), "+f"((c)[1]), "+f"((c)[2]), "+f"((c)[3]) \
        : "r"((a)[0]), "r"((a)[1]), "r"((a)[2]), "r"((a)[3]), \
          "r"((b)[0]), "r"((b)[1]))

// ---------------------------------------------------------------------------
// Kernel 1 (R5 proven, per-batch): x_pw = bn(W @ x) + x, tf32 mma.sync.
// ---------------------------------------------------------------------------
__global__ void __launch_bounds__(256) gemm_pw_kernel(
    const float* __restrict__ x,  const float* __restrict__ w,
    const float* __restrict__ gg, const float* __restrict__ bb,
    const float* __restrict__ mm, const float* __restrict__ vv,
    const int bi)
{
    __shared__ uint32_t sA[2][16][136];
    __shared__ uint32_t sB[2][16][120];

    const int tid = threadIdx.x;
    const int wid = tid >> 5;
    const int lane = tid & 31;
    const int g   = lane >> 2;
    const int tig = lane & 3;
    const int wm  = (wid & 3) * 32;
    const int wn  = (wid >> 2) * 56;

    const int m0 = blockIdx.y * 128;
    const int p0 = blockIdx.x * 112;

    const float* xb = x + (size_t)bi * C_ * HWSZ;

    float acc[2][7][4];
#pragma unroll
    for (int mt = 0; mt < 2; mt++)
#pragma unroll
        for (int nt = 0; nt < 7; nt++)
#pragma unroll
            for (int q = 0; q < 4; q++) acc[mt][nt][q] = 0.f;

    const int aq0 = tid, aq1 = tid + 256;
    const int am0 = aq0 >> 2, akq0 = aq0 & 3;
    const int am1 = aq1 >> 2, akq1 = aq1 & 3;
    const float* wp0 = w + (size_t)(m0 + am0) * C_ + akq0 * 4;
    const float* wp1 = w + (size_t)(m0 + am1) * C_ + akq1 * 4;
    const int bq0 = tid, bq1 = tid + 256;
    const int bkr0 = bq0 / 28, bnq0 = bq0 - bkr0 * 28;
    const int bkr1 = bq1 / 28, bnq1 = bq1 - bkr1 * 28;
    const bool bv1 = bq1 < 448;
    const float* xp0 = xb + (size_t)bkr0 * HWSZ + p0 + bnq0 * 4;
    const float* xp1 = bv1 ? (xb + (size_t)bkr1 * HWSZ + p0 + bnq1 * 4) : xp0;

    {
        float4 a0 = *(const float4*)(wp0);
        float4 a1 = *(const float4*)(wp1);
        sA[0][akq0 * 4 + 0][am0] = cvt_tf32(a0.x);
        sA[0][akq0 * 4 + 1][am0] = cvt_tf32(a0.y);
        sA[0][akq0 * 4 + 2][am0] = cvt_tf32(a0.z);
        sA[0][akq0 * 4 + 3][am0] = cvt_tf32(a0.w);
        sA[0][akq1 * 4 + 0][am1] = cvt_tf32(a1.x);
        sA[0][akq1 * 4 + 1][am1] = cvt_tf32(a1.y);
        sA[0][akq1 * 4 + 2][am1] = cvt_tf32(a1.z);
        sA[0][akq1 * 4 + 3][am1] = cvt_tf32(a1.w);
        float4 b0 = *(const float4*)(xp0);
        uint4 t0 = {cvt_tf32(b0.x), cvt_tf32(b0.y), cvt_tf32(b0.z), cvt_tf32(b0.w)};
        *(uint4*)(&sB[0][bkr0][bnq0 * 4]) = t0;
        if (bv1) {
            float4 b1 = *(const float4*)(xp1);
            uint4 t1 = {cvt_tf32(b1.x), cvt_tf32(b1.y), cvt_tf32(b1.z), cvt_tf32(b1.w)};
            *(uint4*)(&sB[0][bkr1][bnq1 * 4]) = t1;
        }
    }
    __syncthreads();

    for (int kc = 0; kc < 24; kc++) {
        const int buf = kc & 1;
        const bool more = kc < 23;
        float4 pa0, pa1, pb0, pb1;
        if (more) {
            const int kn = (kc + 1) * 16;
            pa0 = *(const float4*)(wp0 + kn);
            pa1 = *(const float4*)(wp1 + kn);
            pb0 = *(const float4*)(xp0 + (size_t)kn * HWSZ);
            if (bv1) pb1 = *(const float4*)(xp1 + (size_t)kn * HWSZ);
        }

#pragma unroll
        for (int kk = 0; kk < 2; kk++) {
            const int kr = kk * 8 + tig;
            const uint32_t* A0 = &sA[buf][kr][wm];
            const uint32_t* A4 = &sA[buf][kr + 4][wm];
            const uint32_t* B0 = &sB[buf][kr][wn];
            const uint32_t* B4 = &sB[buf][kr + 4][wn];
            uint32_t a[2][4], b[7][2];
#pragma unroll
            for (int mt = 0; mt < 2; mt++) {
                a[mt][0] = A0[mt * 16 + g];
                a[mt][1] = A0[mt * 16 + g + 8];
                a[mt][2] = A4[mt * 16 + g];
                a[mt][3] = A4[mt * 16 + g + 8];
            }
#pragma unroll
            for (int nt = 0; nt < 7; nt++) {
                b[nt][0] = B0[nt * 8 + g];
                b[nt][1] = B4[nt * 8 + g];
            }
#pragma unroll
            for (int mt = 0; mt < 2; mt++)
#pragma unroll
                for (int nt = 0; nt < 7; nt++)
                    MMA_TF32(acc[mt][nt], a[mt], b[nt]);
        }

        if (more) {
            const int nb = buf ^ 1;
            sA[nb][akq0 * 4 + 0][am0] = cvt_tf32(pa0.x);
            sA[nb][akq0 * 4 + 1][am0] = cvt_tf32(pa0.y);
            sA[nb][akq0 * 4 + 2][am0] = cvt_tf32(pa0.z);
            sA[nb][akq0 * 4 + 3][am0] = cvt_tf32(pa0.w);
            sA[nb][akq1 * 4 + 0][am1] = cvt_tf32(pa1.x);
            sA[nb][akq1 * 4 + 1][am1] = cvt_tf32(pa1.y);
            sA[nb][akq1 * 4 + 2][am1] = cvt_tf32(pa1.z);
            sA[nb][akq1 * 4 + 3][am1] = cvt_tf32(pa1.w);
            uint4 t0 = {cvt_tf32(pb0.x), cvt_tf32(pb0.y), cvt_tf32(pb0.z), cvt_tf32(pb0.w)};
            *(uint4*)(&sB[nb][bkr0][bnq0 * 4]) = t0;
            if (bv1) {
                uint4 t1 = {cvt_tf32(pb1.x), cvt_tf32(pb1.y), cvt_tf32(pb1.z), cvt_tf32(pb1.w)};
                *(uint4*)(&sB[nb][bkr1][bnq1 * 4]) = t1;
            }
        }
        __syncthreads();
    }

    float sc[2][2], sh[2][2];
#pragma unroll
    for (int mt = 0; mt < 2; mt++)
#pragma unroll
        for (int h = 0; h < 2; h++) {
            const int o = m0 + wm + mt * 16 + h * 8 + g;
            const float s = gg[o] * rsqrtf(vv[o] + EPSV);
            sc[mt][h] = s;
            sh[mt][h] = fmaf(-mm[o], s, bb[o]);
        }

#pragma unroll
    for (int mt = 0; mt < 2; mt++)
#pragma unroll
        for (int h = 0; h < 2; h++) {
            const int o = m0 + wm + mt * 16 + h * 8 + g;
            const size_t rb = ((size_t)bi * C_ + o) * HWSZ + p0 + wn + 2 * tig;
#pragma unroll
            for (int nt = 0; nt < 7; nt++) {
                const size_t idx = rb + nt * 8;
                float2 xr = *(const float2*)(x + idx);
                const float c0 = acc[mt][nt][h * 2 + 0];
                const float c1 = acc[mt][nt][h * 2 + 1];
                float2 ov;
                ov.x = fmaf(c0, sc[mt][h], sh[mt][h]) + xr.x;
                ov.y = fmaf(c1, sc[mt][h], sh[mt][h]) + xr.y;
                *(float2*)(g_xpw + idx) = ov;
            }
        }
}

// ---------------------------------------------------------------------------
// Kernel 2 (R1 proven, per-batch): out = gelu(bn(dwconv13(x_pw)) + bn(x_pw*dw1_w))
// ---------------------------------------------------------------------------
__global__ void __launch_bounds__(224) dw_bn_gelu_kernel(
    const float* __restrict__ kw,
    const float* __restrict__ kg,  const float* __restrict__ kb,
    const float* __restrict__ km,  const float* __restrict__ kv,
    const float* __restrict__ d1w, const float* __restrict__ d1g,
    const float* __restrict__ d1b, const float* __restrict__ d1m,
    const float* __restrict__ d1v,
    float* __restrict__ out, const int bi)
{
    __shared__ float s_in[28 * 72];
    __shared__ float s_w[169];

    const int band = blockIdx.x;
    const int c    = blockIdx.y;
    const int tid  = threadIdx.x;
    const int r0   = band * 16;

    const float* src = g_xpw + ((size_t)bi * C_ + c) * HWSZ;

    for (int idx = tid; idx < 28 * 68; idx += 224) {
        const int row = idx / 68;
        const int col = idx - row * 68;
        const int gh = r0 - 6 + row;
        const int gw = col - 6;
        float val = 0.f;
        if (gh >= 0 && gh < HH && gw >= 0 && gw < WW) val = src[gh * WW + gw];
        s_in[row * 72 + col] = val;
    }
    if (tid < 169) s_w[tid] = kw[(size_t)c * 169 + tid];
    __syncthreads();

    const int tx = tid % 14;
    const int ty = tid / 14;
    const int orow = r0 + ty;
    if (orow >= HH) return;

    const int x4 = tx * 4;
    float acc0 = 0.f, acc1 = 0.f, acc2 = 0.f, acc3 = 0.f;

#pragma unroll
    for (int i = 0; i < 13; i++) {
        const float* rp = s_in + (ty + i) * 72 + x4;
        float r[16];
        *(float4*)&r[0]  = *(const float4*)(rp);
        *(float4*)&r[4]  = *(const float4*)(rp + 4);
        *(float4*)&r[8]  = *(const float4*)(rp + 8);
        *(float4*)&r[12] = *(const float4*)(rp + 12);
#pragma unroll
        for (int j = 0; j < 13; j++) {
            const float wv = s_w[i * 13 + j];
            acc0 = fmaf(r[j + 0], wv, acc0);
            acc1 = fmaf(r[j + 1], wv, acc1);
            acc2 = fmaf(r[j + 2], wv, acc2);
            acc3 = fmaf(r[j + 3], wv, acc3);
        }
    }

    const float sk  = kg[c] * rsqrtf(kv[c] + EPSV);
    const float shk = fmaf(-km[c], sk, kb[c]);
    const float s1  = d1g[c] * rsqrtf(d1v[c] + EPSV);
    const float a2  = d1w[c] * s1;
    const float b2  = fmaf(-d1m[c], s1, d1b[c]);

    const float* cp = s_in + (ty + 6) * 72 + x4 + 6;
    const float v0 = fmaf(acc0, sk, shk) + fmaf(cp[0], a2, b2);
    const float v1 = fmaf(acc1, sk, shk) + fmaf(cp[1], a2, b2);
    const float v2 = fmaf(acc2, sk, shk) + fmaf(cp[2], a2, b2);
    const float v3 = fmaf(acc3, sk, shk) + fmaf(cp[3], a2, b2);

    const float RS2 = 0.70710678118654752f;
    float4 res;
    res.x = 0.5f * v0 * (1.f + erff(v0 * RS2));
    res.y = 0.5f * v1 * (1.f + erff(v1 * RS2));
    res.z = 0.5f * v2 * (1.f + erff(v2 * RS2));
    res.w = 0.5f * v3 * (1.f + erff(v3 * RS2));

    *(float4*)(out + ((size_t)bi * C_ + c) * HWSZ + orow * WW + x4) = res;
}

// ---------------------------------------------------------------------------
// Launch: two-stream software pipeline. GEMM(bi) on sA; dw(bi) on sB waits
// GEMM(bi) -> dw(bi) overlaps GEMM(bi+1). Fork from and join back to the
// caller's (capture) stream via events. Streams/events are host objects
// created once; no device memory is allocated.
// ---------------------------------------------------------------------------
extern "C" void kernel_launch(void* const* d_in, const int* in_sizes, int n_in,
                              void* d_out, int out_size)
{
    const float* x     = (const float*)d_in[0];
    const float* pw_w  = (const float*)d_in[1];
    const float* pw_g  = (const float*)d_in[2];
    const float* pw_b  = (const float*)d_in[3];
    const float* pw_m  = (const float*)d_in[4];
    const float* pw_v  = (const float*)d_in[5];
    const float* dwk_w = (const float*)d_in[6];
    const float* dwk_g = (const float*)d_in[7];
    const float* dwk_b = (const float*)d_in[8];
    const float* dwk_m = (const float*)d_in[9];
    const float* dwk_v = (const float*)d_in[10];
    const float* dw1_w = (const float*)d_in[11];
    const float* dw1_g = (const float*)d_in[12];
    const float* dw1_b = (const float*)d_in[13];
    const float* dw1_m = (const float*)d_in[14];
    const float* dw1_v = (const float*)d_in[15];
    float* out = (float*)d_out;

    static cudaStream_t sA = 0, sB = 0;
    static cudaEvent_t evFork = 0, evJoinA = 0, evJoinB = 0;
    static cudaEvent_t evG[NB];
    if (sA == 0) {
        cudaStreamCreateWithFlags(&sA, cudaStreamNonBlocking);
        cudaStreamCreateWithFlags(&sB, cudaStreamNonBlocking);
        cudaEventCreateWithFlags(&evFork, cudaEventDisableTiming);
        cudaEventCreateWithFlags(&evJoinA, cudaEventDisableTiming);
        cudaEventCreateWithFlags(&evJoinB, cudaEventDisableTiming);
        for (int i = 0; i < NB; i++)
            cudaEventCreateWithFlags(&evG[i], cudaEventDisableTiming);
    }

    // fork from the caller's stream
    cudaEventRecord(evFork, 0);
    cudaStreamWaitEvent(sA, evFork, 0);
    cudaStreamWaitEvent(sB, evFork, 0);

    dim3 gg(HWSZ / 112, C_ / 128);   // (28, 3)
    dim3 gd((HH + 15) / 16, C_);     // (4, 384)
    for (int bi = 0; bi < NB; bi++) {
        gemm_pw_kernel<<<gg, 256, 0, sA>>>(x, pw_w, pw_g, pw_b, pw_m, pw_v, bi);
        cudaEventRecord(evG[bi], sA);
        cudaStreamWaitEvent(sB, evG[bi], 0);
        dw_bn_gelu_kernel<<<gd, 224, 0, sB>>>(dwk_w, dwk_g, dwk_b, dwk_m, dwk_v,
                                              dw1_w, dw1_g, dw1_b, dw1_m, dw1_v,
                                              out, bi);
    }

    // join both forks back into the caller's stream
    cudaEventRecord(evJoinA, sA);
    cudaEventRecord(evJoinB, sB);
    cudaStreamWaitEvent(0, evJoinA, 0);
    cudaStreamWaitEvent(0, evJoinB, 0);
}

// round 16
// speedup vs baseline: 1.5336x; 1.5336x over previous
#include <cuda_runtime.h>
#include <math.h>
#include <stdint.h>

#define C_    384
#define HH    56
#define WW    56
#define HWSZ  3136
#define NB    16
#define CHUNK 4
#define EPSV  1e-5f

// Scratch for x_pw: 16*384*3136 floats = 77 MB
__device__ float g_xpw[(size_t)NB * C_ * HWSZ];

__device__ __forceinline__ uint32_t cvt_tf32(float f) {
    uint32_t r;
    asm("cvt.rna.tf32.f32 %0, %1;" : "=r"(r) : "f"(f));
    return r;
}

#define MMA_TF32(c, a, b) \
    asm volatile("mma.sync.aligned.m16n8k8.row.col.f32.tf32.tf32.f32 " \
        "{%0,%1,%2,%3}, {%4,%5,%6,%7}, {%8,%9}, {%0,%1,%2,%3};" \
        : "+f"((c)[0]), "+f"((c)[1]), "+f"((c)[2]), "+f"((c)[3]) \
        : "r"((a)[0]), "r"((a)[1]), "r"((a)[2]), "r"((a)[3]), \
          "r"((b)[0]), "r"((b)[1]))

// ---------------------------------------------------------------------------
// Kernel 1 (R5 proven): x_pw = bn(W @ x) + x, tf32 mma.sync. bi = b0 + blockIdx.z
// ---------------------------------------------------------------------------
__global__ void __launch_bounds__(256) gemm_pw_kernel(
    const float* __restrict__ x,  const float* __restrict__ w,
    const float* __restrict__ gg, const float* __restrict__ bb,
    const float* __restrict__ mm, const float* __restrict__ vv,
    const int b0)
{
    __shared__ uint32_t sA[2][16][136];
    __shared__ uint32_t sB[2][16][120];

    const int tid = threadIdx.x;
    const int wid = tid >> 5;
    const int lane = tid & 31;
    const int g   = lane >> 2;
    const int tig = lane & 3;
    const int wm  = (wid & 3) * 32;
    const int wn  = (wid >> 2) * 56;

    const int bi = b0 + blockIdx.z;
    const int m0 = blockIdx.y * 128;
    const int p0 = blockIdx.x * 112;

    const float* xb = x + (size_t)bi * C_ * HWSZ;

    float acc[2][7][4];
#pragma unroll
    for (int mt = 0; mt < 2; mt++)
#pragma unroll
        for (int nt = 0; nt < 7; nt++)
#pragma unroll
            for (int q = 0; q < 4; q++) acc[mt][nt][q] = 0.f;

    const int aq0 = tid, aq1 = tid + 256;
    const int am0 = aq0 >> 2, akq0 = aq0 & 3;
    const int am1 = aq1 >> 2, akq1 = aq1 & 3;
    const float* wp0 = w + (size_t)(m0 + am0) * C_ + akq0 * 4;
    const float* wp1 = w + (size_t)(m0 + am1) * C_ + akq1 * 4;
    const int bq0 = tid, bq1 = tid + 256;
    const int bkr0 = bq0 / 28, bnq0 = bq0 - bkr0 * 28;
    const int bkr1 = bq1 / 28, bnq1 = bq1 - bkr1 * 28;
    const bool bv1 = bq1 < 448;
    const float* xp0 = xb + (size_t)bkr0 * HWSZ + p0 + bnq0 * 4;
    const float* xp1 = bv1 ? (xb + (size_t)bkr1 * HWSZ + p0 + bnq1 * 4) : xp0;

    {
        float4 a0 = *(const float4*)(wp0);
        float4 a1 = *(const float4*)(wp1);
        sA[0][akq0 * 4 + 0][am0] = cvt_tf32(a0.x);
        sA[0][akq0 * 4 + 1][am0] = cvt_tf32(a0.y);
        sA[0][akq0 * 4 + 2][am0] = cvt_tf32(a0.z);
        sA[0][akq0 * 4 + 3][am0] = cvt_tf32(a0.w);
        sA[0][akq1 * 4 + 0][am1] = cvt_tf32(a1.x);
        sA[0][akq1 * 4 + 1][am1] = cvt_tf32(a1.y);
        sA[0][akq1 * 4 + 2][am1] = cvt_tf32(a1.z);
        sA[0][akq1 * 4 + 3][am1] = cvt_tf32(a1.w);
        float4 b0v = *(const float4*)(xp0);
        uint4 t0 = {cvt_tf32(b0v.x), cvt_tf32(b0v.y), cvt_tf32(b0v.z), cvt_tf32(b0v.w)};
        *(uint4*)(&sB[0][bkr0][bnq0 * 4]) = t0;
        if (bv1) {
            float4 b1 = *(const float4*)(xp1);
            uint4 t1 = {cvt_tf32(b1.x), cvt_tf32(b1.y), cvt_tf32(b1.z), cvt_tf32(b1.w)};
            *(uint4*)(&sB[0][bkr1][bnq1 * 4]) = t1;
        }
    }
    __syncthreads();

    for (int kc = 0; kc < 24; kc++) {
        const int buf = kc & 1;
        const bool more = kc < 23;
        float4 pa0, pa1, pb0, pb1;
        if (more) {
            const int kn = (kc + 1) * 16;
            pa0 = *(const float4*)(wp0 + kn);
            pa1 = *(const float4*)(wp1 + kn);
            pb0 = *(const float4*)(xp0 + (size_t)kn * HWSZ);
            if (bv1) pb1 = *(const float4*)(xp1 + (size_t)kn * HWSZ);
        }

#pragma unroll
        for (int kk = 0; kk < 2; kk++) {
            const int kr = kk * 8 + tig;
            const uint32_t* A0 = &sA[buf][kr][wm];
            const uint32_t* A4 = &sA[buf][kr + 4][wm];
            const uint32_t* B0 = &sB[buf][kr][wn];
            const uint32_t* B4 = &sB[buf][kr + 4][wn];
            uint32_t a[2][4], b[7][2];
#pragma unroll
            for (int mt = 0; mt < 2; mt++) {
                a[mt][0] = A0[mt * 16 + g];
                a[mt][1] = A0[mt * 16 + g + 8];
                a[mt][2] = A4[mt * 16 + g];
                a[mt][3] = A4[mt * 16 + g + 8];
            }
#pragma unroll
            for (int nt = 0; nt < 7; nt++) {
                b[nt][0] = B0[nt * 8 + g];
                b[nt][1] = B4[nt * 8 + g];
            }
#pragma unroll
            for (int mt = 0; mt < 2; mt++)
#pragma unroll
                for (int nt = 0; nt < 7; nt++)
                    MMA_TF32(acc[mt][nt], a[mt], b[nt]);
        }

        if (more) {
            const int nb = buf ^ 1;
            sA[nb][akq0 * 4 + 0][am0] = cvt_tf32(pa0.x);
            sA[nb][akq0 * 4 + 1][am0] = cvt_tf32(pa0.y);
            sA[nb][akq0 * 4 + 2][am0] = cvt_tf32(pa0.z);
            sA[nb][akq0 * 4 + 3][am0] = cvt_tf32(pa0.w);
            sA[nb][akq1 * 4 + 0][am1] = cvt_tf32(pa1.x);
            sA[nb][akq1 * 4 + 1][am1] = cvt_tf32(pa1.y);
            sA[nb][akq1 * 4 + 2][am1] = cvt_tf32(pa1.z);
            sA[nb][akq1 * 4 + 3][am1] = cvt_tf32(pa1.w);
            uint4 t0 = {cvt_tf32(pb0.x), cvt_tf32(pb0.y), cvt_tf32(pb0.z), cvt_tf32(pb0.w)};
            *(uint4*)(&sB[nb][bkr0][bnq0 * 4]) = t0;
            if (bv1) {
                uint4 t1 = {cvt_tf32(pb1.x), cvt_tf32(pb1.y), cvt_tf32(pb1.z), cvt_tf32(pb1.w)};
                *(uint4*)(&sB[nb][bkr1][bnq1 * 4]) = t1;
            }
        }
        __syncthreads();
    }

    float sc[2][2], sh[2][2];
#pragma unroll
    for (int mt = 0; mt < 2; mt++)
#pragma unroll
        for (int h = 0; h < 2; h++) {
            const int o = m0 + wm + mt * 16 + h * 8 + g;
            const float s = gg[o] * rsqrtf(vv[o] + EPSV);
            sc[mt][h] = s;
            sh[mt][h] = fmaf(-mm[o], s, bb[o]);
        }

#pragma unroll
    for (int mt = 0; mt < 2; mt++)
#pragma unroll
        for (int h = 0; h < 2; h++) {
            const int o = m0 + wm + mt * 16 + h * 8 + g;
            const size_t rb = ((size_t)bi * C_ + o) * HWSZ + p0 + wn + 2 * tig;
#pragma unroll
            for (int nt = 0; nt < 7; nt++) {
                const size_t idx = rb + nt * 8;
                float2 xr = *(const float2*)(x + idx);
                const float c0 = acc[mt][nt][h * 2 + 0];
                const float c1 = acc[mt][nt][h * 2 + 1];
                float2 ov;
                ov.x = fmaf(c0, sc[mt][h], sh[mt][h]) + xr.x;
                ov.y = fmaf(c1, sc[mt][h], sh[mt][h]) + xr.y;
                *(float2*)(g_xpw + idx) = ov;
            }
        }
}

// ---------------------------------------------------------------------------
// Kernel 2 (R1 proven): out = gelu(bn(dwconv13(x_pw)) + bn(x_pw*dw1_w))
// bi = b0 + blockIdx.z
// ---------------------------------------------------------------------------
__global__ void __launch_bounds__(224) dw_bn_gelu_kernel(
    const float* __restrict__ kw,
    const float* __restrict__ kg,  const float* __restrict__ kb,
    const float* __restrict__ km,  const float* __restrict__ kv,
    const float* __restrict__ d1w, const float* __restrict__ d1g,
    const float* __restrict__ d1b, const float* __restrict__ d1m,
    const float* __restrict__ d1v,
    float* __restrict__ out, const int b0)
{
    __shared__ float s_in[28 * 72];
    __shared__ float s_w[169];

    const int band = blockIdx.x;
    const int c    = blockIdx.y;
    const int bi   = b0 + blockIdx.z;
    const int tid  = threadIdx.x;
    const int r0   = band * 16;

    const float* src = g_xpw + ((size_t)bi * C_ + c) * HWSZ;

    for (int idx = tid; idx < 28 * 68; idx += 224) {
        const int row = idx / 68;
        const int col = idx - row * 68;
        const int gh = r0 - 6 + row;
        const int gw = col - 6;
        float val = 0.f;
        if (gh >= 0 && gh < HH && gw >= 0 && gw < WW) val = src[gh * WW + gw];
        s_in[row * 72 + col] = val;
    }
    if (tid < 169) s_w[tid] = kw[(size_t)c * 169 + tid];
    __syncthreads();

    const int tx = tid % 14;
    const int ty = tid / 14;
    const int orow = r0 + ty;
    if (orow >= HH) return;

    const int x4 = tx * 4;
    float acc0 = 0.f, acc1 = 0.f, acc2 = 0.f, acc3 = 0.f;

#pragma unroll
    for (int i = 0; i < 13; i++) {
        const float* rp = s_in + (ty + i) * 72 + x4;
        float r[16];
        *(float4*)&r[0]  = *(const float4*)(rp);
        *(float4*)&r[4]  = *(const float4*)(rp + 4);
        *(float4*)&r[8]  = *(const float4*)(rp + 8);
        *(float4*)&r[12] = *(const float4*)(rp + 12);
#pragma unroll
        for (int j = 0; j < 13; j++) {
            const float wv = s_w[i * 13 + j];
            acc0 = fmaf(r[j + 0], wv, acc0);
            acc1 = fmaf(r[j + 1], wv, acc1);
            acc2 = fmaf(r[j + 2], wv, acc2);
            acc3 = fmaf(r[j + 3], wv, acc3);
        }
    }

    const float sk  = kg[c] * rsqrtf(kv[c] + EPSV);
    const float shk = fmaf(-km[c], sk, kb[c]);
    const float s1  = d1g[c] * rsqrtf(d1v[c] + EPSV);
    const float a2  = d1w[c] * s1;
    const float b2  = fmaf(-d1m[c], s1, d1b[c]);

    const float* cp = s_in + (ty + 6) * 72 + x4 + 6;
    const float v0 = fmaf(acc0, sk, shk) + fmaf(cp[0], a2, b2);
    const float v1 = fmaf(acc1, sk, shk) + fmaf(cp[1], a2, b2);
    const float v2 = fmaf(acc2, sk, shk) + fmaf(cp[2], a2, b2);
    const float v3 = fmaf(acc3, sk, shk) + fmaf(cp[3], a2, b2);

    const float RS2 = 0.70710678118654752f;
    float4 res;
    res.x = 0.5f * v0 * (1.f + erff(v0 * RS2));
    res.y = 0.5f * v1 * (1.f + erff(v1 * RS2));
    res.z = 0.5f * v2 * (1.f + erff(v2 * RS2));
    res.w = 0.5f * v3 * (1.f + erff(v3 * RS2));

    *(float4*)(out + ((size_t)bi * C_ + c) * HWSZ + orow * WW + x4) = res;
}

// ---------------------------------------------------------------------------
// Launch: chunked two-stream pipeline (chunk = 4 batches).
// GEMM(chunk c) on sA -> event -> dw(chunk c) on sB, overlapping GEMM(c+1).
// Fork from / join back to the caller's (capture) stream via events.
// Streams/events are host objects created once; no device memory allocated.
// ---------------------------------------------------------------------------
extern "C" void kernel_launch(void* const* d_in, const int* in_sizes, int n_in,
                              void* d_out, int out_size)
{
    const float* x     = (const float*)d_in[0];
    const float* pw_w  = (const float*)d_in[1];
    const float* pw_g  = (const float*)d_in[2];
    const float* pw_b  = (const float*)d_in[3];
    const float* pw_m  = (const float*)d_in[4];
    const float* pw_v  = (const float*)d_in[5];
    const float* dwk_w = (const float*)d_in[6];
    const float* dwk_g = (const float*)d_in[7];
    const float* dwk_b = (const float*)d_in[8];
    const float* dwk_m = (const float*)d_in[9];
    const float* dwk_v = (const float*)d_in[10];
    const float* dw1_w = (const float*)d_in[11];
    const float* dw1_g = (const float*)d_in[12];
    const float* dw1_b = (const float*)d_in[13];
    const float* dw1_m = (const float*)d_in[14];
    const float* dw1_v = (const float*)d_in[15];
    float* out = (float*)d_out;

    static cudaStream_t sA = 0, sB = 0;
    static cudaEvent_t evFork = 0, evJoinA = 0, evJoinB = 0;
    static cudaEvent_t evG[NB / CHUNK];
    if (sA == 0) {
        cudaStreamCreateWithFlags(&sA, cudaStreamNonBlocking);
        cudaStreamCreateWithFlags(&sB, cudaStreamNonBlocking);
        cudaEventCreateWithFlags(&evFork, cudaEventDisableTiming);
        cudaEventCreateWithFlags(&evJoinA, cudaEventDisableTiming);
        cudaEventCreateWithFlags(&evJoinB, cudaEventDisableTiming);
        for (int i = 0; i < NB / CHUNK; i++)
            cudaEventCreateWithFlags(&evG[i], cudaEventDisableTiming);
    }

    // fork from the caller's stream
    cudaEventRecord(evFork, 0);
    cudaStreamWaitEvent(sA, evFork, 0);
    cudaStreamWaitEvent(sB, evFork, 0);

    dim3 gg(HWSZ / 112, C_ / 128, CHUNK);   // (28, 3, 4)
    dim3 gd((HH + 15) / 16, C_, CHUNK);     // (4, 384, 4)
    for (int c = 0; c < NB / CHUNK; c++) {
        const int b0 = c * CHUNK;
        gemm_pw_kernel<<<gg, 256, 0, sA>>>(x, pw_w, pw_g, pw_b, pw_m, pw_v, b0);
        cudaEventRecord(evG[c], sA);
        cudaStreamWaitEvent(sB, evG[c], 0);
        dw_bn_gelu_kernel<<<gd, 224, 0, sB>>>(dwk_w, dwk_g, dwk_b, dwk_m, dwk_v,
                                              dw1_w, dw1_g, dw1_b, dw1_m, dw1_v,
                                              out, b0);
    }

    // join both forks back into the caller's stream
    cudaEventRecord(evJoinA, sA);
    cudaEventRecord(evJoinB, sB);
    cudaStreamWaitEvent(0, evJoinA, 0);
    cudaStreamWaitEvent(0, evJoinB, 0);
}

// round 17
// speedup vs baseline: 1.8703x; 1.2195x over previous
#include <cuda_runtime.h>
#include <cuda_fp16.h>
#include <math.h>
#include <stdint.h>

#define C_    384
#define HH    56
#define WW    56
#define HWSZ  3136
#define NB    16
#define EPSV  1e-5f

// Scratch for x_pw: 16*384*3136 floats = 77 MB
__device__ float g_xpw[(size_t)NB * C_ * HWSZ];

__device__ __forceinline__ uint32_t h2(float lo, float hi) {
    __half2 h = __floats2half2_rn(lo, hi);
    return *(uint32_t*)&h;
}

#define MMA_F16(c, a, b) \
    asm volatile("mma.sync.aligned.m16n8k16.row.col.f32.f16.f16.f32 " \
        "{%0,%1,%2,%3}, {%4,%5,%6,%7}, {%8,%9}, {%0,%1,%2,%3};" \
        : "+f"((c)[0]), "+f"((c)[1]), "+f"((c)[2]), "+f"((c)[3]) \
        : "r"((a)[0]), "r"((a)[1]), "r"((a)[2]), "r"((a)[3]), \
          "r"((b)[0]), "r"((b)[1]))

// ---------------------------------------------------------------------------
// Kernel 1 v3: x_pw = bn(W @ x) + x.  fp16 m16n8k16 mma (fp32 accum).
// CTA: M=128 x N=112, K=384, BK=16, double-buffered register prefetch.
// sA[m][kpair] stride 12 half2-words (banks 12g+tig: all-distinct);
// sB[kpair][n] stride 120 (banks 24tig+g: all-distinct).
// Accumulator layout identical to the proven tf32 kernel -> same epilogue.
// ---------------------------------------------------------------------------
__global__ void __launch_bounds__(256) gemm_pw_kernel(
    const float* __restrict__ x,  const float* __restrict__ w,
    const float* __restrict__ gg, const float* __restrict__ bb,
    const float* __restrict__ mm, const float* __restrict__ vv)
{
    __shared__ uint32_t sA[2][128][12];   // [buf][m][kp] (8 used per row)
    __shared__ uint32_t sB[2][8][120];    // [buf][kp][n] (112 used)

    const int tid = threadIdx.x;
    const int wid = tid >> 5;
    const int lane = tid & 31;
    const int g   = lane >> 2;
    const int tig = lane & 3;
    const int wm  = (wid & 3) * 32;
    const int wn  = (wid >> 2) * 56;

    const int bi = blockIdx.z;
    const int m0 = blockIdx.y * 128;
    const int p0 = blockIdx.x * 112;

    const float* xb = x + (size_t)bi * C_ * HWSZ;

    float acc[2][7][4];
#pragma unroll
    for (int mt = 0; mt < 2; mt++)
#pragma unroll
        for (int nt = 0; nt < 7; nt++)
#pragma unroll
            for (int q = 0; q < 4; q++) acc[mt][nt][q] = 0.f;

    // A staging roles: tasks q0 = tid, q1 = tid+256 over 512 float4s
    const int am0 = tid >> 2,         akq = tid & 3;
    const int am1 = (tid + 256) >> 2;                  // akq identical
    const float* wp0 = w + (size_t)(m0 + am0) * C_ + akq * 4;
    const float* wp1 = w + (size_t)(m0 + am1) * C_ + akq * 4;
    // B staging roles: t < 224: kp = t/28, nq = t%28; loads rows 2kp, 2kp+1
    const int bkp = tid / 28, bnq = tid - bkp * 28;
    const bool bact = tid < 224;
    const float* xp0 = bact ? (xb + (size_t)(2 * bkp) * HWSZ + p0 + bnq * 4) : xb;
    const float* xp1 = xp0 + HWSZ;

    // ---- preload chunk 0 into buffer 0 ----
    {
        float4 a0 = *(const float4*)(wp0);
        float4 a1 = *(const float4*)(wp1);
        sA[0][am0][akq * 2 + 0] = h2(a0.x, a0.y);
        sA[0][am0][akq * 2 + 1] = h2(a0.z, a0.w);
        sA[0][am1][akq * 2 + 0] = h2(a1.x, a1.y);
        sA[0][am1][akq * 2 + 1] = h2(a1.z, a1.w);
        if (bact) {
            float4 r0 = *(const float4*)(xp0);
            float4 r1 = *(const float4*)(xp1);
            uint4 t = {h2(r0.x, r1.x), h2(r0.y, r1.y), h2(r0.z, r1.z), h2(r0.w, r1.w)};
            *(uint4*)(&sB[0][bkp][bnq * 4]) = t;
        }
    }
    __syncthreads();

    for (int kc = 0; kc < 24; kc++) {
        const int buf = kc & 1;
        const bool more = kc < 23;
        float4 pa0, pa1, pb0, pb1;
        if (more) {
            const int kn = (kc + 1) * 16;
            pa0 = *(const float4*)(wp0 + kn);
            pa1 = *(const float4*)(wp1 + kn);
            if (bact) {
                pb0 = *(const float4*)(xp0 + (size_t)kn * HWSZ);
                pb1 = *(const float4*)(xp1 + (size_t)kn * HWSZ);
            }
        }

        // ---- one m16n8k16 step (full BK=16) ----
        {
            uint32_t a[2][4], b[7][2];
#pragma unroll
            for (int mt = 0; mt < 2; mt++) {
                const uint32_t* ap = &sA[buf][wm + mt * 16 + g][0];
                a[mt][0] = ap[tig];
                a[mt][1] = ap[8 * 12 + tig];        // row +8
                a[mt][2] = ap[tig + 4];
                a[mt][3] = ap[8 * 12 + tig + 4];
            }
            const uint32_t* bp0 = &sB[buf][tig][wn + g];
            const uint32_t* bp4 = &sB[buf][tig + 4][wn + g];
#pragma unroll
            for (int nt = 0; nt < 7; nt++) {
                b[nt][0] = bp0[nt * 8];
                b[nt][1] = bp4[nt * 8];
            }
#pragma unroll
            for (int mt = 0; mt < 2; mt++)
#pragma unroll
                for (int nt = 0; nt < 7; nt++)
                    MMA_F16(acc[mt][nt], a[mt], b[nt]);
        }

        if (more) {
            const int nb = buf ^ 1;
            sA[nb][am0][akq * 2 + 0] = h2(pa0.x, pa0.y);
            sA[nb][am0][akq * 2 + 1] = h2(pa0.z, pa0.w);
            sA[nb][am1][akq * 2 + 0] = h2(pa1.x, pa1.y);
            sA[nb][am1][akq * 2 + 1] = h2(pa1.z, pa1.w);
            if (bact) {
                uint4 t = {h2(pb0.x, pb1.x), h2(pb0.y, pb1.y),
                           h2(pb0.z, pb1.z), h2(pb0.w, pb1.w)};
                *(uint4*)(&sB[nb][bkp][bnq * 4]) = t;
            }
        }
        __syncthreads();
    }

    // ---- epilogue: BN + residual -> g_xpw (same acc layout as tf32) ----
    float sc[2][2], sh[2][2];
#pragma unroll
    for (int mt = 0; mt < 2; mt++)
#pragma unroll
        for (int h = 0; h < 2; h++) {
            const int o = m0 + wm + mt * 16 + h * 8 + g;
            const float s = gg[o] * rsqrtf(vv[o] + EPSV);
            sc[mt][h] = s;
            sh[mt][h] = fmaf(-mm[o], s, bb[o]);
        }

#pragma unroll
    for (int mt = 0; mt < 2; mt++)
#pragma unroll
        for (int h = 0; h < 2; h++) {
            const int o = m0 + wm + mt * 16 + h * 8 + g;
            const size_t rb = ((size_t)bi * C_ + o) * HWSZ + p0 + wn + 2 * tig;
#pragma unroll
            for (int nt = 0; nt < 7; nt++) {
                const size_t idx = rb + nt * 8;
                float2 xr = *(const float2*)(x + idx);
                const float c0 = acc[mt][nt][h * 2 + 0];
                const float c1 = acc[mt][nt][h * 2 + 1];
                float2 ov;
                ov.x = fmaf(c0, sc[mt][h], sh[mt][h]) + xr.x;
                ov.y = fmaf(c1, sc[mt][h], sh[mt][h]) + xr.y;
                *(float2*)(g_xpw + idx) = ov;
            }
        }
}

// ---------------------------------------------------------------------------
// Kernel 2 (R1 proven, 236us): out = gelu(bn(dwconv13(x_pw)) + bn(x_pw*dw1_w))
// ---------------------------------------------------------------------------
__global__ void __launch_bounds__(224) dw_bn_gelu_kernel(
    const float* __restrict__ kw,
    const float* __restrict__ kg,  const float* __restrict__ kb,
    const float* __restrict__ km,  const float* __restrict__ kv,
    const float* __restrict__ d1w, const float* __restrict__ d1g,
    const float* __restrict__ d1b, const float* __restrict__ d1m,
    const float* __restrict__ d1v,
    float* __restrict__ out)
{
    __shared__ float s_in[28 * 72];
    __shared__ float s_w[169];

    const int band = blockIdx.x;
    const int c    = blockIdx.y;
    const int bi   = blockIdx.z;
    const int tid  = threadIdx.x;
    const int r0   = band * 16;

    const float* src = g_xpw + ((size_t)bi * C_ + c) * HWSZ;

    for (int idx = tid; idx < 28 * 68; idx += 224) {
        const int row = idx / 68;
        const int col = idx - row * 68;
        const int gh = r0 - 6 + row;
        const int gw = col - 6;
        float val = 0.f;
        if (gh >= 0 && gh < HH && gw >= 0 && gw < WW) val = src[gh * WW + gw];
        s_in[row * 72 + col] = val;
    }
    if (tid < 169) s_w[tid] = kw[(size_t)c * 169 + tid];
    __syncthreads();

    const int tx = tid % 14;
    const int ty = tid / 14;
    const int orow = r0 + ty;
    if (orow >= HH) return;

    const int x4 = tx * 4;
    float acc0 = 0.f, acc1 = 0.f, acc2 = 0.f, acc3 = 0.f;

#pragma unroll
    for (int i = 0; i < 13; i++) {
        const float* rp = s_in + (ty + i) * 72 + x4;
        float r[16];
        *(float4*)&r[0]  = *(const float4*)(rp);
        *(float4*)&r[4]  = *(const float4*)(rp + 4);
        *(float4*)&r[8]  = *(const float4*)(rp + 8);
        *(float4*)&r[12] = *(const float4*)(rp + 12);
#pragma unroll
        for (int j = 0; j < 13; j++) {
            const float wv = s_w[i * 13 + j];
            acc0 = fmaf(r[j + 0], wv, acc0);
            acc1 = fmaf(r[j + 1], wv, acc1);
            acc2 = fmaf(r[j + 2], wv, acc2);
            acc3 = fmaf(r[j + 3], wv, acc3);
        }
    }

    const float sk  = kg[c] * rsqrtf(kv[c] + EPSV);
    const float shk = fmaf(-km[c], sk, kb[c]);
    const float s1  = d1g[c] * rsqrtf(d1v[c] + EPSV);
    const float a2  = d1w[c] * s1;
    const float b2  = fmaf(-d1m[c], s1, d1b[c]);

    const float* cp = s_in + (ty + 6) * 72 + x4 + 6;
    const float v0 = fmaf(acc0, sk, shk) + fmaf(cp[0], a2, b2);
    const float v1 = fmaf(acc1, sk, shk) + fmaf(cp[1], a2, b2);
    const float v2 = fmaf(acc2, sk, shk) + fmaf(cp[2], a2, b2);
    const float v3 = fmaf(acc3, sk, shk) + fmaf(cp[3], a2, b2);

    const float RS2 = 0.70710678118654752f;
    float4 res;
    res.x = 0.5f * v0 * (1.f + erff(v0 * RS2));
    res.y = 0.5f * v1 * (1.f + erff(v1 * RS2));
    res.z = 0.5f * v2 * (1.f + erff(v2 * RS2));
    res.w = 0.5f * v3 * (1.f + erff(v3 * RS2));

    *(float4*)(out + ((size_t)bi * C_ + c) * HWSZ + orow * WW + x4) = res;
}

// ---------------------------------------------------------------------------
extern "C" void kernel_launch(void* const* d_in, const int* in_sizes, int n_in,
                              void* d_out, int out_size)
{
    const float* x     = (const float*)d_in[0];
    const float* pw_w  = (const float*)d_in[1];
    const float* pw_g  = (const float*)d_in[2];
    const float* pw_b  = (const float*)d_in[3];
    const float* pw_m  = (const float*)d_in[4];
    const float* pw_v  = (const float*)d_in[5];
    const float* dwk_w = (const float*)d_in[6];
    const float* dwk_g = (const float*)d_in[7];
    const float* dwk_b = (const float*)d_in[8];
    const float* dwk_m = (const float*)d_in[9];
    const float* dwk_v = (const float*)d_in[10];
    const float* dw1_w = (const float*)d_in[11];
    const float* dw1_g = (const float*)d_in[12];
    const float* dw1_b = (const float*)d_in[13];
    const float* dw1_m = (const float*)d_in[14];
    const float* dw1_v = (const float*)d_in[15];
    float* out = (float*)d_out;

    dim3 g1(HWSZ / 112, C_ / 128, NB);   // (28, 3, 16)
    gemm_pw_kernel<<<g1, 256>>>(x, pw_w, pw_g, pw_b, pw_m, pw_v);

    dim3 g2((HH + 15) / 16, C_, NB);     // (4, 384, 16)
    dw_bn_gelu_kernel<<<g2, 224>>>(dwk_w, dwk_g, dwk_b, dwk_m, dwk_v,
                                   dw1_w, dw1_g, dw1_b, dw1_m, dw1_v, out);
}